// round 14
// baseline (speedup 1.0000x reference)
#include <cuda_runtime.h>
#include <cuda_fp16.h>
#include <math.h>
#include <stdint.h>

#define N_ROWS  65536
#define CDIM    256
#define KCODES  1024
#define HW      4096

#define OFF_ZQ   1
#define OFF_IDX  (1 + 16777216)
#define OFF_PERP (1 + 16777216 + 65536)

#define GT 256            // gemm threads (8 warps)
#define BM 128            // rows per CTA (warp owns 16)
#define BNC 32            // codes per chunk
#define NCHUNKS 32
#define B_CHUNK_B 16384   // 32 codes x 512 B
#define GEMM_DYN 98304    // 64KB A + 2x16KB B

// fp16 codebook mirror
__device__ __align__(16) __half g_ef16[(size_t)KCODES * CDIM];
__device__ float  g_ee[KCODES];
__device__ int    g_idx[N_ROWS];
__device__ int    g_cnt[KCODES];
__device__ double g_loss;

// ---------------- PTX helpers (baseline ISA only) ----------------
__device__ __forceinline__ uint32_t smem_u32(const void* p) {
    uint32_t a;
    asm("{ .reg .u64 t; cvta.to.shared.u64 t, %1; cvt.u32.u64 %0, t; }" : "=r"(a) : "l"(p));
    return a;
}
__device__ __forceinline__ void cp16(uint32_t dst, const void* src) {
    asm volatile("cp.async.cg.shared.global [%0], [%1], 16;" :: "r"(dst), "l"(src));
}
#define CP_COMMIT() asm volatile("cp.async.commit_group;" ::: "memory")
#define CP_WAIT0()  asm volatile("cp.async.wait_group 0;" ::: "memory")

__device__ __forceinline__ void ldsm4(uint32_t& r0, uint32_t& r1, uint32_t& r2,
                                      uint32_t& r3, uint32_t addr) {
    asm volatile("ldmatrix.sync.aligned.m8n8.x4.shared.b16 {%0,%1,%2,%3}, [%4];"
                 : "=r"(r0), "=r"(r1), "=r"(r2), "=r"(r3) : "r"(addr));
}
__device__ __forceinline__ void mma16816(float* c, const uint32_t* a,
                                         uint32_t b0, uint32_t b1) {
    asm volatile(
        "mma.sync.aligned.m16n8k16.row.col.f32.f16.f16.f32 "
        "{%0,%1,%2,%3}, {%4,%5,%6,%7}, {%8,%9}, {%0,%1,%2,%3};"
        : "+f"(c[0]), "+f"(c[1]), "+f"(c[2]), "+f"(c[3])
        : "r"(a[0]), "r"(a[1]), "r"(a[2]), "r"(a[3]), "r"(b0), "r"(b1));
}

// ---------------------------------------------------------------------------
__global__ void k_nop() {}   // profiler-slot fillers: keep k_gemm at launch idx 3

// ---------------------------------------------------------------------------
// K1: e -> fp16 mirror + ee (double), zero counters. grid 4 x 256.
// ---------------------------------------------------------------------------
__global__ void k_prep(const float* __restrict__ e) {
    const int code = blockIdx.x * 256 + threadIdx.x;
    const float* er = e + (size_t)code * CDIM;
    __half* hr = g_ef16 + (size_t)code * CDIM;
    double s = 0.0;
    for (int c8 = 0; c8 < CDIM; c8 += 8) {
        float v[8];
        *(float4*)&v[0] = *(const float4*)(er + c8);
        *(float4*)&v[4] = *(const float4*)(er + c8 + 4);
        __half2 h[4];
        #pragma unroll
        for (int i = 0; i < 4; i++) h[i] = __floats2half2_rn(v[2*i], v[2*i+1]);
        *(uint4*)(hr + c8) = *(uint4*)h;
        #pragma unroll
        for (int i = 0; i < 8; i++) s += (double)v[i] * (double)v[i];
    }
    g_ee[code]  = (float)s;
    g_cnt[code] = 0;
    if (code == 0) g_loss = 0.0;
}

// ---------------------------------------------------------------------------
// top-2 helpers (branchless hot-loop UPD; ascending codes -> strict < is
// first-occurrence; d==v1 ties land in v2 and force the recheck).
// ---------------------------------------------------------------------------
#define UPD_FAST(v1, i1, v2, i2, d, cd) do { \
    bool _p = (d) < (v1); \
    bool _q = (d) < (v2); \
    (v2) = _p ? (v1) : (_q ? (d) : (v2)); \
    (i2) = _p ? (i1) : (_q ? (cd) : (i2)); \
    (v1) = _p ? (d) : (v1); \
    (i1) = _p ? (cd) : (i1); \
    } while (0)

__device__ __forceinline__ void merge_pair(float& v1, int& i1, float& v2, int& i2,
                                           float w1, int j1, float w2, int j2) {
    if (w1 < v1 || (w1 == v1 && j1 < i1)) {
        v2 = v1; i2 = i1; v1 = w1; i1 = j1;
        if (w2 < v2 || (w2 == v2 && j2 < i2)) { v2 = w2; i2 = j2; }
    } else if (w1 < v2 || (w1 == v2 && j1 < i2)) {
        v2 = w1; i2 = j1;
    }
}

__device__ __forceinline__ void merge_quad(float& v1, int& i1, float& v2, int& i2) {
    #pragma unroll
    for (int m = 1; m <= 2; m <<= 1) {
        float w1 = __shfl_xor_sync(0xffffffffu, v1, m);
        int   j1 = __shfl_xor_sync(0xffffffffu, i1, m);
        float w2 = __shfl_xor_sync(0xffffffffu, v2, m);
        int   j2 = __shfl_xor_sync(0xffffffffu, i2, m);
        merge_pair(v1, i1, v2, i2, w1, j1, w2, j2);
    }
}

__device__ __forceinline__ void finalize_row(int row, float v1, int i1,
                                             float v2, int i2, float zzv,
                                             const float* __restrict__ z,
                                             const float* __restrict__ e,
                                             float* __restrict__ out_idx) {
    if (v2 - v1 < 1e-4f) {
        const float* zr = z + (size_t)(row >> 12) * (CDIM * HW) + (row & 4095);
        const float* e1 = e + (size_t)i1 * CDIM;
        const float* e2 = e + (size_t)i2 * CDIM;
        float a1 = 0.0f, a2 = 0.0f;
        for (int c = 0; c < CDIM; c++) {
            float zv = zr[(size_t)c * HW];
            a1 = fmaf(zv, e1[c], a1);
            a2 = fmaf(zv, e2[c], a2);
        }
        // exact fp32 rounding sequence of the reference for both candidates
        float d1 = __fsub_rn(__fadd_rn(zzv, g_ee[i1]), __fmul_rn(2.0f, a1));
        float d2 = __fsub_rn(__fadd_rn(zzv, g_ee[i2]), __fmul_rn(2.0f, a2));
        if (d2 < d1 || (d2 == d1 && i2 < i1)) i1 = i2;
    }
    g_idx[row]   = i1;
    out_idx[row] = (float)i1;
    atomicAdd(&g_cnt[i1], 1);
}

// ---------------------------------------------------------------------------
// K2: fp16 HMMA GEMM + fused argmin, in-prologue z transpose/convert.
// 512 CTAs x 256 thr (8 warps x 16 rows), 2 CTAs/SM -> 16 warps/SM
// (4/SMSP, vs 3 in R11-R13) at the exact 128-reg/thread RF point.
// A (128x256 fp16, XOR-swizzled) built in-kernel; B in 32 chunks of 32
// codes, double-buffered cp.async. Per-warp body = R11 (proven).
// In-loop d: fmaf(-2, acc, zz+ee) == reference rounding grid (2*acc exact).
// ---------------------------------------------------------------------------
__global__ __launch_bounds__(GT, 2) void k_gemm(
    const float* __restrict__ z, const float* __restrict__ e,
    float* __restrict__ out_idx)
{
    extern __shared__ char dsm[];
    __shared__ float ee_s[KCODES];
    __shared__ float zz_s[BM];
    __shared__ float zzp[BM][2];

    const uint32_t sA = smem_u32(dsm);          // 65536 B
    const uint32_t sB = sA + 65536;             // 2 x 16384 B
    const int tid = threadIdx.x, wid = tid >> 5, lane = tid & 31;
    const int n0 = blockIdx.x * BM;

    // kick off B chunk 0 first so it overlaps the A conversion below
    const char* gB = (const char*)g_ef16;
    #pragma unroll
    for (int it = 0; it < 4; it++) {
        int i = it * GT + tid, r = i >> 5, u = i & 31;
        cp16(sB + r * 512 + ((u ^ (r & 7)) << 4), gB + (size_t)r * 512 + u * 16);
    }
    CP_COMMIT();

    for (int i = tid; i < KCODES; i += GT) ee_s[i] = g_ee[i];

    // ---- A prologue: load 128 z rows (f32, coalesced), convert to fp16,
    //      store swizzled; accumulate zz partials (fp32 fmaf ascending). ----
    {
        const int hw = tid & 127;               // local row
        const int ch = tid >> 7;                // channel half (0..1)
        const int b = n0 >> 12, hw0 = n0 & 4095;
        const float* zb = z + (size_t)b * (CDIM * HW) + hw0 + hw;
        const uint32_t rowbase = sA + hw * 512;
        const int rx = hw & 7;
        float s = 0.0f;
        #pragma unroll
        for (int u8 = 0; u8 < 16; u8++) {       // 16 units of 8 channels
            int c0 = ch * 128 + u8 * 8;
            float v[8];
            #pragma unroll
            for (int i = 0; i < 8; i++) {
                v[i] = zb[(size_t)(c0 + i) * HW];
                s = fmaf(v[i], v[i], s);
            }
            __half2 h[4];
            #pragma unroll
            for (int i = 0; i < 4; i++) h[i] = __floats2half2_rn(v[2*i], v[2*i+1]);
            int u = ch * 16 + u8;
            uint32_t addr = rowbase + (((uint32_t)u ^ (uint32_t)rx) << 4);
            asm volatile("st.shared.v4.b32 [%0], {%1,%2,%3,%4};"
                         :: "r"(addr), "r"(*(uint32_t*)&h[0]), "r"(*(uint32_t*)&h[1]),
                            "r"(*(uint32_t*)&h[2]), "r"(*(uint32_t*)&h[3]) : "memory");
        }
        zzp[hw][ch] = s;
    }
    CP_WAIT0();
    __syncthreads();
    if (tid < BM) zz_s[tid] = zzp[tid][0] + zzp[tid][1];
    __syncthreads();

    // per-warp / per-lane geometry (warp owns rows wid*16 .. wid*16+15)
    const int wr0 = wid * 16;
    const int lrow = wr0 + (lane >> 2);               // local rows lrow, lrow+8
    const float zzA = zz_s[lrow], zzB = zz_s[lrow + 8];

    const int amr = wr0 + (lane & 15);
    const uint32_t aBase = sA + amr * 512;
    const uint32_t arx = amr & 7;
    const uint32_t aku = (lane >> 4) & 1;
    const int bnl = (lane & 7) + ((lane & 16) ? 8 : 0);
    const uint32_t bku = (lane >> 3) & 1;
    const uint32_t brx = bnl & 7;
    uint32_t bOff[2];
    #pragma unroll
    for (int np = 0; np < 2; np++)
        bOff[np] = (uint32_t)(np * 16 + bnl) * 512;

    // two accumulator sets per row: [row(0=A,1=B)][set(nt<2, nt>=2)]
    float v1[2][2], v2[2][2];
    int   i1[2][2], i2[2][2];
    #pragma unroll
    for (int r = 0; r < 2; r++)
        #pragma unroll
        for (int st = 0; st < 2; st++) {
            v1[r][st] = INFINITY; v2[r][st] = INFINITY;
            i1[r][st] = 0;        i2[r][st] = 0;
        }

    for (int cc = 0; cc < NCHUNKS; cc++) {
        const uint32_t curB = sB + (cc & 1) * B_CHUNK_B;
        if (cc < NCHUNKS - 1) {
            const char* src = gB + (size_t)(cc + 1) * B_CHUNK_B;
            const uint32_t dstB = sB + ((cc + 1) & 1) * B_CHUNK_B;
            #pragma unroll
            for (int it = 0; it < 4; it++) {
                int i = it * GT + tid, r = i >> 5, u = i & 31;
                cp16(dstB + r * 512 + ((u ^ (r & 7)) << 4),
                     src + (size_t)r * 512 + u * 16);
            }
            CP_COMMIT();
        }

        float c[4][4];
        #pragma unroll
        for (int nt = 0; nt < 4; nt++)
            #pragma unroll
            for (int q = 0; q < 4; q++) c[nt][q] = 0.0f;

        #pragma unroll
        for (int ks = 0; ks < 16; ks++) {
            uint32_t a0[4];
            uint32_t au = (uint32_t)(ks * 2) + aku;
            ldsm4(a0[0], a0[1], a0[2], a0[3], aBase + ((au ^ arx) << 4));
            uint32_t bm[2][4];
            uint32_t bu = (uint32_t)(ks * 2) + bku;
            #pragma unroll
            for (int np = 0; np < 2; np++)
                ldsm4(bm[np][0], bm[np][1], bm[np][2], bm[np][3],
                      curB + bOff[np] + ((bu ^ brx) << 4));
            #pragma unroll
            for (int nt = 0; nt < 4; nt++)
                mma16816(c[nt], a0,
                         bm[nt >> 1][(nt & 1) * 2], bm[nt >> 1][(nt & 1) * 2 + 1]);
        }

        // epilogue: d = fmaf(-2, acc, zz+ee) == reference rounding grid
        #pragma unroll
        for (int nt = 0; nt < 4; nt++) {
            const int st = nt >> 1;
            int code0 = cc * BNC + nt * 8 + ((lane & 3) << 1);
            float e0 = ee_s[code0], e1 = ee_s[code0 + 1];
            float tA0 = __fadd_rn(zzA, e0), tA1 = __fadd_rn(zzA, e1);
            float tB0 = __fadd_rn(zzB, e0), tB1 = __fadd_rn(zzB, e1);
            float d;
            d = fmaf(-2.0f, c[nt][0], tA0);
            UPD_FAST(v1[0][st], i1[0][st], v2[0][st], i2[0][st], d, code0);
            d = fmaf(-2.0f, c[nt][1], tA1);
            UPD_FAST(v1[0][st], i1[0][st], v2[0][st], i2[0][st], d, code0 + 1);
            d = fmaf(-2.0f, c[nt][2], tB0);
            UPD_FAST(v1[1][st], i1[1][st], v2[1][st], i2[1][st], d, code0);
            d = fmaf(-2.0f, c[nt][3], tB1);
            UPD_FAST(v1[1][st], i1[1][st], v2[1][st], i2[1][st], d, code0 + 1);
        }

        if (cc < NCHUNKS - 1) CP_WAIT0();
        __syncthreads();
    }

    // merge set1 into set0 (index-aware), then across the quad lanes
    #pragma unroll
    for (int r = 0; r < 2; r++) {
        merge_pair(v1[r][0], i1[r][0], v2[r][0], i2[r][0],
                   v1[r][1], i1[r][1], v2[r][1], i2[r][1]);
        merge_quad(v1[r][0], i1[r][0], v2[r][0], i2[r][0]);
    }
    if ((lane & 3) == 0) {
        finalize_row(n0 + lrow,     v1[0][0], i1[0][0], v2[0][0], i2[0][0], zzA, z, e, out_idx);
        finalize_row(n0 + lrow + 8, v1[1][0], i1[1][0], v2[1][0], i2[1][0], zzB, z, e, out_idx);
    }
}

// ---------------------------------------------------------------------------
// K3: codebook scatter + loss (fp32 accum, double only at the atomic).
// ---------------------------------------------------------------------------
__global__ __launch_bounds__(256) void k_scatter(
    const float* __restrict__ z, const float* __restrict__ e,
    float* __restrict__ out_zq)
{
    __shared__ int   sid[64];
    __shared__ float sred[256];
    const int tid = threadIdx.x;
    const int n0 = blockIdx.x * 64;
    const int b = n0 >> 12, hw0 = n0 & 4095;
    if (tid < 64) sid[tid] = g_idx[n0 + tid];
    __syncthreads();
    const int m = tid & 63, q = tid >> 6;
    const int cbase = q * 64;
    const float* zbase = z      + (size_t)b * (CDIM * HW) + hw0 + m + (size_t)cbase * HW;
    float*       obase = out_zq + (size_t)b * (CDIM * HW) + hw0 + m + (size_t)cbase * HW;
    const float* erow  = e + (size_t)sid[m] * CDIM + cbase;

    float s = 0.0f;
    #pragma unroll 4
    for (int j = 0; j < 64; j += 4) {
        float4 ev = *(const float4*)(erow + j);
        float evv[4] = {ev.x, ev.y, ev.z, ev.w};
        #pragma unroll
        for (int i = 0; i < 4; i++) {
            float zv = zbase[(size_t)(j + i) * HW];
            float df = __fsub_rn(evv[i], zv);
            obase[(size_t)(j + i) * HW] = __fadd_rn(zv, df);
            s = fmaf(df, df, s);
        }
    }
    sred[tid] = s;
    __syncthreads();
    #pragma unroll
    for (int off = 128; off; off >>= 1) {
        if (tid < off) sred[tid] += sred[tid + off];
        __syncthreads();
    }
    if (tid == 0) atomicAdd(&g_loss, (double)sred[0]);
}

__global__ void k_final(float* __restrict__ out) {
    __shared__ float sred[KCODES];
    int t = threadIdx.x;
    float p = (float)g_cnt[t] * (1.0f / 65536.0f);
    sred[t] = p * logf(p + 1e-10f);
    __syncthreads();
    #pragma unroll
    for (int off = 512; off; off >>= 1) {
        if (t < off) sred[t] += sred[t + off];
        __syncthreads();
    }
    if (t == 0) {
        out[0]        = (float)(g_loss * (1.25 / 16777216.0));
        out[OFF_PERP] = expf(-sred[0]);
    }
}

// ---------------------------------------------------------------------------
extern "C" void kernel_launch(void* const* d_in, const int* in_sizes, int n_in,
                              void* d_out, int out_size) {
    const float* z = (const float*)d_in[0];
    const float* e = (const float*)d_in[1];
    if (n_in >= 2 && in_sizes[0] < in_sizes[1]) {
        z = (const float*)d_in[1];
        e = (const float*)d_in[0];
    }
    float* out = (float*)d_out;

    static int smem_set = 0;
    if (!smem_set) {
        cudaFuncSetAttribute(k_gemm, cudaFuncAttributeMaxDynamicSharedMemorySize, GEMM_DYN);
        smem_set = 1;
    }

    k_prep   <<<4,    256>>>(e);
    k_nop    <<<1,    32>>>();          // fillers keep k_gemm at captured idx 3
    k_nop    <<<1,    32>>>();
    k_gemm   <<<512,  GT, GEMM_DYN>>>(z, e, out + OFF_IDX);
    k_scatter<<<1024, 256>>>(z, e, out + OFF_ZQ);
    k_final  <<<1,   KCODES>>>(out);
}

// round 15
// speedup vs baseline: 1.0991x; 1.0991x over previous
#include <cuda_runtime.h>
#include <cuda_fp16.h>
#include <math.h>
#include <stdint.h>

#define N_ROWS  65536
#define CDIM    256
#define KCODES  1024
#define HW      4096

#define OFF_ZQ   1
#define OFF_IDX  (1 + 16777216)
#define OFF_PERP (1 + 16777216 + 65536)

#define GT 128            // gemm threads (4 warps)
#define BM 64             // rows per CTA
#define BNC 32            // codes per chunk
#define NCHUNKS 32
#define B_CHUNK_B 16384   // 32 codes x 512 B
#define GEMM_DYN 65536    // 32KB A + 2x16KB B

// fp16 codebook mirror
__device__ __align__(16) __half g_ef16[(size_t)KCODES * CDIM];
__device__ float  g_ee[KCODES];
__device__ int    g_cnt[KCODES];
__device__ double g_loss;

// ---------------- PTX helpers (baseline ISA only) ----------------
__device__ __forceinline__ uint32_t smem_u32(const void* p) {
    uint32_t a;
    asm("{ .reg .u64 t; cvta.to.shared.u64 t, %1; cvt.u32.u64 %0, t; }" : "=r"(a) : "l"(p));
    return a;
}
__device__ __forceinline__ void cp16(uint32_t dst, const void* src) {
    asm volatile("cp.async.cg.shared.global [%0], [%1], 16;" :: "r"(dst), "l"(src));
}
#define CP_COMMIT() asm volatile("cp.async.commit_group;" ::: "memory")
#define CP_WAIT0()  asm volatile("cp.async.wait_group 0;" ::: "memory")

__device__ __forceinline__ void ldsm4(uint32_t& r0, uint32_t& r1, uint32_t& r2,
                                      uint32_t& r3, uint32_t addr) {
    asm volatile("ldmatrix.sync.aligned.m8n8.x4.shared.b16 {%0,%1,%2,%3}, [%4];"
                 : "=r"(r0), "=r"(r1), "=r"(r2), "=r"(r3) : "r"(addr));
}
__device__ __forceinline__ void mma16816(float* c, const uint32_t* a,
                                         uint32_t b0, uint32_t b1) {
    asm volatile(
        "mma.sync.aligned.m16n8k16.row.col.f32.f16.f16.f32 "
        "{%0,%1,%2,%3}, {%4,%5,%6,%7}, {%8,%9}, {%0,%1,%2,%3};"
        : "+f"(c[0]), "+f"(c[1]), "+f"(c[2]), "+f"(c[3])
        : "r"(a[0]), "r"(a[1]), "r"(a[2]), "r"(a[3]), "r"(b0), "r"(b1));
}

// ---------------------------------------------------------------------------
__global__ void k_nop() {}   // profiler-slot fillers: keep k_gemm at launch idx 3

// ---------------------------------------------------------------------------
// K1: e -> fp16 mirror + ee (double), zero counters. grid 4 x 256.
// ---------------------------------------------------------------------------
__global__ void k_prep(const float* __restrict__ e) {
    const int code = blockIdx.x * 256 + threadIdx.x;
    const float* er = e + (size_t)code * CDIM;
    __half* hr = g_ef16 + (size_t)code * CDIM;
    double s = 0.0;
    for (int c8 = 0; c8 < CDIM; c8 += 8) {
        float v[8];
        *(float4*)&v[0] = *(const float4*)(er + c8);
        *(float4*)&v[4] = *(const float4*)(er + c8 + 4);
        __half2 h[4];
        #pragma unroll
        for (int i = 0; i < 4; i++) h[i] = __floats2half2_rn(v[2*i], v[2*i+1]);
        *(uint4*)(hr + c8) = *(uint4*)h;
        #pragma unroll
        for (int i = 0; i < 8; i++) s += (double)v[i] * (double)v[i];
    }
    g_ee[code]  = (float)s;
    g_cnt[code] = 0;
    if (code == 0) g_loss = 0.0;
}

// ---------------------------------------------------------------------------
// top-2 helpers (branchless hot-loop UPD; ascending codes -> strict < is
// first-occurrence; d==v1 ties land in v2 and force the recheck).
// ---------------------------------------------------------------------------
#define UPD_FAST(v1, i1, v2, i2, d, cd) do { \
    bool _p = (d) < (v1); \
    bool _q = (d) < (v2); \
    (v2) = _p ? (v1) : (_q ? (d) : (v2)); \
    (i2) = _p ? (i1) : (_q ? (cd) : (i2)); \
    (v1) = _p ? (d) : (v1); \
    (i1) = _p ? (cd) : (i1); \
    } while (0)

__device__ __forceinline__ void merge_pair(float& v1, int& i1, float& v2, int& i2,
                                           float w1, int j1, float w2, int j2) {
    if (w1 < v1 || (w1 == v1 && j1 < i1)) {
        v2 = v1; i2 = i1; v1 = w1; i1 = j1;
        if (w2 < v2 || (w2 == v2 && j2 < i2)) { v2 = w2; i2 = j2; }
    } else if (w1 < v2 || (w1 == v2 && j1 < i2)) {
        v2 = w1; i2 = j1;
    }
}

__device__ __forceinline__ void merge_quad(float& v1, int& i1, float& v2, int& i2) {
    #pragma unroll
    for (int m = 1; m <= 2; m <<= 1) {
        float w1 = __shfl_xor_sync(0xffffffffu, v1, m);
        int   j1 = __shfl_xor_sync(0xffffffffu, i1, m);
        float w2 = __shfl_xor_sync(0xffffffffu, v2, m);
        int   j2 = __shfl_xor_sync(0xffffffffu, i2, m);
        merge_pair(v1, i1, v2, i2, w1, j1, w2, j2);
    }
}

// returns the final argmin index (near-tie resolved with the reference's
// exact fp32 rounding sequence)
__device__ __forceinline__ int resolve_row(int row, float v1, int i1,
                                           float v2, int i2, float zzv,
                                           const float* __restrict__ z,
                                           const float* __restrict__ e) {
    if (v2 - v1 < 1e-4f) {
        const float* zr = z + (size_t)(row >> 12) * (CDIM * HW) + (row & 4095);
        const float* e1 = e + (size_t)i1 * CDIM;
        const float* e2 = e + (size_t)i2 * CDIM;
        float a1 = 0.0f, a2 = 0.0f;
        for (int c = 0; c < CDIM; c++) {
            float zv = zr[(size_t)c * HW];
            a1 = fmaf(zv, e1[c], a1);
            a2 = fmaf(zv, e2[c], a2);
        }
        float d1 = __fsub_rn(__fadd_rn(zzv, g_ee[i1]), __fmul_rn(2.0f, a1));
        float d2 = __fsub_rn(__fadd_rn(zzv, g_ee[i2]), __fmul_rn(2.0f, a2));
        if (d2 < d1 || (d2 == d1 && i2 < i1)) i1 = i2;
    }
    return i1;
}

// ---------------------------------------------------------------------------
// K2: fp16 HMMA GEMM + fused argmin + FUSED scatter/loss.
// 1024 CTAs x 128 thr, 3 CTAs/SM. GEMM body = R13 (split-K, half A-reg-cache).
// After the argmin, the SAME CTA scatters e[idx] -> z_q for its 64 rows and
// accumulates the loss — its DRAM traffic hides under other CTAs' gemm.
// ---------------------------------------------------------------------------
__global__ __launch_bounds__(GT, 3) void k_gemm(
    const float* __restrict__ z, const float* __restrict__ e,
    float* __restrict__ out_idx, float* __restrict__ out_zq)
{
    extern __shared__ char dsm[];
    __shared__ float ee_s[KCODES];
    __shared__ float zz_s[64];
    __shared__ float zzp[64][2];
    __shared__ int   sid[64];
    __shared__ float sred[GT];

    const uint32_t sA = smem_u32(dsm);          // 32768 B
    const uint32_t sB = sA + 32768;             // 2 x 16384 B
    const int tid = threadIdx.x, wid = tid >> 5, lane = tid & 31;
    const int n0 = blockIdx.x * BM;
    const int gb = n0 >> 12, ghw0 = n0 & 4095;

    // kick off B chunk 0 first so it overlaps the A conversion below
    const char* gB = (const char*)g_ef16;
    #pragma unroll
    for (int it = 0; it < 8; it++) {
        int i = it * GT + tid, r = i >> 5, u = i & 31;
        cp16(sB + r * 512 + ((u ^ (r & 7)) << 4), gB + (size_t)r * 512 + u * 16);
    }
    CP_COMMIT();

    for (int i = tid; i < KCODES; i += GT) ee_s[i] = g_ee[i];

    // ---- A prologue: load 64 z rows (f32, coalesced), convert to fp16,
    //      store swizzled; accumulate zz partials (fp32 fmaf ascending). ----
    {
        const int hw = tid & 63;
        const int ch = tid >> 6;
        const float* zb = z + (size_t)gb * (CDIM * HW) + ghw0 + hw;
        const uint32_t rowbase = sA + hw * 512;
        const int rx = hw & 7;
        float s = 0.0f;
        #pragma unroll
        for (int u8 = 0; u8 < 16; u8++) {
            int c0 = ch * 128 + u8 * 8;
            float v[8];
            #pragma unroll
            for (int i = 0; i < 8; i++) {
                v[i] = zb[(size_t)(c0 + i) * HW];
                s = fmaf(v[i], v[i], s);
            }
            __half2 h[4];
            #pragma unroll
            for (int i = 0; i < 4; i++) h[i] = __floats2half2_rn(v[2*i], v[2*i+1]);
            int u = ch * 16 + u8;
            uint32_t addr = rowbase + (((uint32_t)u ^ (uint32_t)rx) << 4);
            asm volatile("st.shared.v4.b32 [%0], {%1,%2,%3,%4};"
                         :: "r"(addr), "r"(*(uint32_t*)&h[0]), "r"(*(uint32_t*)&h[1]),
                            "r"(*(uint32_t*)&h[2]), "r"(*(uint32_t*)&h[3]) : "memory");
        }
        zzp[hw][ch] = s;
    }
    CP_WAIT0();
    __syncthreads();
    if (tid < 64) zz_s[tid] = zzp[tid][0] + zzp[tid][1];
    __syncthreads();

    // per-warp / per-lane geometry (warp owns rows wid*16 .. wid*16+15)
    const int wr0 = wid * 16;
    const int lrow = wr0 + (lane >> 2);               // local rows lrow, lrow+8
    const float zzA = zz_s[lrow], zzB = zz_s[lrow + 8];

    const int amr = wr0 + (lane & 15);
    const uint32_t aBase = sA + amr * 512;
    const uint32_t arx = amr & 7;
    const uint32_t aku = (lane >> 4) & 1;
    const int bnl = (lane & 7) + ((lane & 16) ? 8 : 0);
    const uint32_t bku = (lane >> 3) & 1;
    const uint32_t brx = bnl & 7;
    uint32_t bOff[2];
    #pragma unroll
    for (int np = 0; np < 2; np++)
        bOff[np] = (uint32_t)(np * 16 + bnl) * 512;

    // cache A fragments for ks 0..7 (32 regs)
    uint32_t aF[8][4];
    #pragma unroll
    for (int ks = 0; ks < 8; ks++) {
        uint32_t au = (uint32_t)(ks * 2) + aku;
        ldsm4(aF[ks][0], aF[ks][1], aF[ks][2], aF[ks][3],
              aBase + ((au ^ arx) << 4));
    }

    float v1[2][2], v2[2][2];
    int   i1[2][2], i2[2][2];
    #pragma unroll
    for (int r = 0; r < 2; r++)
        #pragma unroll
        for (int st = 0; st < 2; st++) {
            v1[r][st] = INFINITY; v2[r][st] = INFINITY;
            i1[r][st] = 0;        i2[r][st] = 0;
        }

    for (int cc = 0; cc < NCHUNKS; cc++) {
        const uint32_t curB = sB + (cc & 1) * B_CHUNK_B;
        if (cc < NCHUNKS - 1) {
            const char* src = gB + (size_t)(cc + 1) * B_CHUNK_B;
            const uint32_t dstB = sB + ((cc + 1) & 1) * B_CHUNK_B;
            #pragma unroll
            for (int it = 0; it < 8; it++) {
                int i = it * GT + tid, r = i >> 5, u = i & 31;
                cp16(dstB + r * 512 + ((u ^ (r & 7)) << 4),
                     src + (size_t)r * 512 + u * 16);
            }
            CP_COMMIT();
        }

        float c0[4][4], c1[4][4];
        #pragma unroll
        for (int nt = 0; nt < 4; nt++)
            #pragma unroll
            for (int q = 0; q < 4; q++) { c0[nt][q] = 0.0f; c1[nt][q] = 0.0f; }

        #pragma unroll
        for (int ksp = 0; ksp < 8; ksp++) {
            uint32_t bm0[2][4], bm1[2][4], a1r[4];
            uint32_t bu0 = (uint32_t)(ksp * 2) + bku;
            uint32_t bu1 = (uint32_t)((ksp + 8) * 2) + bku;
            uint32_t au1 = (uint32_t)((ksp + 8) * 2) + aku;
            ldsm4(a1r[0], a1r[1], a1r[2], a1r[3], aBase + ((au1 ^ arx) << 4));
            #pragma unroll
            for (int np = 0; np < 2; np++) {
                ldsm4(bm0[np][0], bm0[np][1], bm0[np][2], bm0[np][3],
                      curB + bOff[np] + ((bu0 ^ brx) << 4));
                ldsm4(bm1[np][0], bm1[np][1], bm1[np][2], bm1[np][3],
                      curB + bOff[np] + ((bu1 ^ brx) << 4));
            }
            #pragma unroll
            for (int nt = 0; nt < 4; nt++) {
                mma16816(c0[nt], aF[ksp],
                         bm0[nt >> 1][(nt & 1) * 2], bm0[nt >> 1][(nt & 1) * 2 + 1]);
                mma16816(c1[nt], a1r,
                         bm1[nt >> 1][(nt & 1) * 2], bm1[nt >> 1][(nt & 1) * 2 + 1]);
            }
        }

        // epilogue: cf = c0 + c1 (exact-safe), d = fmaf(-2, cf, zz+ee)
        #pragma unroll
        for (int nt = 0; nt < 4; nt++) {
            const int st = nt >> 1;
            int code0 = cc * BNC + nt * 8 + ((lane & 3) << 1);
            float e0 = ee_s[code0], e1 = ee_s[code0 + 1];
            float tA0 = __fadd_rn(zzA, e0), tA1 = __fadd_rn(zzA, e1);
            float tB0 = __fadd_rn(zzB, e0), tB1 = __fadd_rn(zzB, e1);
            float cf0 = __fadd_rn(c0[nt][0], c1[nt][0]);
            float cf1 = __fadd_rn(c0[nt][1], c1[nt][1]);
            float cf2 = __fadd_rn(c0[nt][2], c1[nt][2]);
            float cf3 = __fadd_rn(c0[nt][3], c1[nt][3]);
            float d;
            d = fmaf(-2.0f, cf0, tA0);
            UPD_FAST(v1[0][st], i1[0][st], v2[0][st], i2[0][st], d, code0);
            d = fmaf(-2.0f, cf1, tA1);
            UPD_FAST(v1[0][st], i1[0][st], v2[0][st], i2[0][st], d, code0 + 1);
            d = fmaf(-2.0f, cf2, tB0);
            UPD_FAST(v1[1][st], i1[1][st], v2[1][st], i2[1][st], d, code0);
            d = fmaf(-2.0f, cf3, tB1);
            UPD_FAST(v1[1][st], i1[1][st], v2[1][st], i2[1][st], d, code0 + 1);
        }

        if (cc < NCHUNKS - 1) CP_WAIT0();
        __syncthreads();
    }

    // merge set1 into set0 (index-aware), then across the quad lanes
    #pragma unroll
    for (int r = 0; r < 2; r++) {
        merge_pair(v1[r][0], i1[r][0], v2[r][0], i2[r][0],
                   v1[r][1], i1[r][1], v2[r][1], i2[r][1]);
        merge_quad(v1[r][0], i1[r][0], v2[r][0], i2[r][0]);
    }
    if ((lane & 3) == 0) {
        int ra = resolve_row(n0 + lrow,     v1[0][0], i1[0][0], v2[0][0], i2[0][0], zzA, z, e);
        int rb = resolve_row(n0 + lrow + 8, v1[1][0], i1[1][0], v2[1][0], i2[1][0], zzB, z, e);
        sid[lrow]            = ra;
        sid[lrow + 8]        = rb;
        out_idx[n0 + lrow]     = (float)ra;
        out_idx[n0 + lrow + 8] = (float)rb;
        atomicAdd(&g_cnt[ra], 1);
        atomicAdd(&g_cnt[rb], 1);
    }
    __syncthreads();

    // ---- fused scatter + loss (identical math to the verified k_scatter) ----
    {
        const int m = tid & 63, half = tid >> 6;
        const int cbase = half * 128;
        const float* zbase = z      + (size_t)gb * (CDIM * HW) + ghw0 + m + (size_t)cbase * HW;
        float*       obase = out_zq + (size_t)gb * (CDIM * HW) + ghw0 + m + (size_t)cbase * HW;
        const float* erow  = e + (size_t)sid[m] * CDIM + cbase;

        float s = 0.0f;
        #pragma unroll 4
        for (int j = 0; j < 128; j += 4) {
            float4 ev = *(const float4*)(erow + j);
            float evv[4] = {ev.x, ev.y, ev.z, ev.w};
            #pragma unroll
            for (int i = 0; i < 4; i++) {
                float zv = zbase[(size_t)(j + i) * HW];
                float df = __fsub_rn(evv[i], zv);
                obase[(size_t)(j + i) * HW] = __fadd_rn(zv, df);
                s = fmaf(df, df, s);
            }
        }
        sred[tid] = s;
        __syncthreads();
        #pragma unroll
        for (int off = 64; off; off >>= 1) {
            if (tid < off) sred[tid] += sred[tid + off];
            __syncthreads();
        }
        if (tid == 0) atomicAdd(&g_loss, (double)sred[0]);
    }
}

__global__ void k_final(float* __restrict__ out) {
    __shared__ float sred[KCODES];
    int t = threadIdx.x;
    float p = (float)g_cnt[t] * (1.0f / 65536.0f);
    sred[t] = p * logf(p + 1e-10f);
    __syncthreads();
    #pragma unroll
    for (int off = 512; off; off >>= 1) {
        if (t < off) sred[t] += sred[t + off];
        __syncthreads();
    }
    if (t == 0) {
        out[0]        = (float)(g_loss * (1.25 / 16777216.0));
        out[OFF_PERP] = expf(-sred[0]);
    }
}

// ---------------------------------------------------------------------------
extern "C" void kernel_launch(void* const* d_in, const int* in_sizes, int n_in,
                              void* d_out, int out_size) {
    const float* z = (const float*)d_in[0];
    const float* e = (const float*)d_in[1];
    if (n_in >= 2 && in_sizes[0] < in_sizes[1]) {
        z = (const float*)d_in[1];
        e = (const float*)d_in[0];
    }
    float* out = (float*)d_out;

    static int smem_set = 0;
    if (!smem_set) {
        cudaFuncSetAttribute(k_gemm, cudaFuncAttributeMaxDynamicSharedMemorySize, GEMM_DYN);
        smem_set = 1;
    }

    k_prep <<<4,    256>>>(e);
    k_nop  <<<1,    32>>>();          // fillers keep k_gemm at captured idx 3
    k_nop  <<<1,    32>>>();
    k_gemm <<<1024, GT, GEMM_DYN>>>(z, e, out + OFF_IDX, out + OFF_ZQ);
    k_final<<<1,   KCODES>>>(out);
}